// round 12
// baseline (speedup 1.0000x reference)
#include <cuda_runtime.h>
#include <math.h>

#define IMG 256
#define NVERT 642
#define NFACE 1280
#define NBATCH 2
#define SHARP (2.0f * (float)IMG)
#define TAU 0.04f    // sigmoid(SHARP*TAU) >= 1 - 1.3e-9: later faces can't change output

// Per-warp autonomous renderer, one CTA per SM, 1 px/lane.
// Block 1024 = 32 warps; block covers 4 rows x 256 px = 1024 px.
// Grid (IMG*IMG/1024, NBATCH) = (64, 2) = 128 CTAs (<=148 SMs -> single wave).
// Warp covers 32 px of row tile*4 + (w>>3); lane -> one pixel.
// Each round: 32 lanes compute coefficients for 32 faces (one each, py folded in),
// __syncwarp, pixel loop with a saturation vote every 8 faces. No block barriers.
__global__ __launch_bounds__(1024) void fused_kernel(const float* __restrict__ verts,
                                                     const int* __restrict__ faces,
                                                     const float* __restrict__ cams,
                                                     float* __restrict__ out) {
    const int b    = blockIdx.y;
    const int tile = blockIdx.x;
    const int t    = threadIdx.x;
    const int w    = t >> 5;          // warp id in block (0..31)
    const int lane = t & 31;

    // Per-warp coefficient slab: [warp][face][2] float4 = (A1,A2,A3,t1),(t2,t3,o,pad)
    __shared__ __align__(16) float4 sw[32][32][2];

    // ---- camera constants (broadcast loads; independent of face loads below)
    const float* cam = cams + b * 7;
    float s   = cam[0];
    float tcx = cam[1];
    float tcy = cam[2];
    float qw = cam[3], qx = cam[4], qy = cam[5], qz = cam[6];
    float qn = rsqrtf(qw * qw + qx * qx + qy * qy + qz * qz);
    qw *= qn; qx *= qn; qy *= qn; qz *= qn;
    const float r00 = 1.f - 2.f * (qy * qy + qz * qz);
    const float r01 = 2.f * (qx * qy - qw * qz);
    const float r02 = 2.f * (qx * qz + qw * qy);
    const float r10 = 2.f * (qx * qy + qw * qz);
    const float r11 = 1.f - 2.f * (qx * qx + qz * qz);
    const float r12 = 2.f * (qy * qz - qw * qx);

    const float* vbase = verts + (size_t)b * NVERT * 3;
    const int*   fbase = faces + (size_t)b * NFACE * 3;

    // ---- pixel mapping: 4 rows/tile, 8 warps/row, 32 px/warp, 1 px/lane
    const int row = tile * 4 + (w >> 3);
    const int x   = (w & 7) * 32 + lane;
    const float inv = 2.0f / (float)IMG;
    const float py = ((float)row + 0.5f) * inv - 1.0f;     // warp-uniform
    const float px = ((float)x   + 0.5f) * inv - 1.0f;
    float acc = -3.402823466e+38f;

    bool done = false;
    for (int c = 0; c < NFACE && !done; c += 32) {
        // ---- this lane computes full coefficients for face (c + lane)
        {
            const int* fi = fbase + (size_t)(c + lane) * 3;
            const int i0 = fi[0];
            const int i1 = fi[1];
            const int i2 = fi[2];

            const float* v0 = vbase + (size_t)i0 * 3;
            const float* v1 = vbase + (size_t)i1 * 3;
            const float* v2 = vbase + (size_t)i2 * 3;
            float aX = v0[0], aY = v0[1], aZ = v0[2];
            float bX = v1[0], bY = v1[1], bZ = v1[2];
            float cX = v2[0], cY = v2[1], cZ = v2[2];

            float x0 =  s * (r00 * aX + r01 * aY + r02 * aZ) + tcx;
            float y0 = -(s * (r10 * aX + r11 * aY + r12 * aZ) + tcy);
            float x1 =  s * (r00 * bX + r01 * bY + r02 * bZ) + tcx;
            float y1 = -(s * (r10 * bX + r11 * bY + r12 * bZ) + tcy);
            float x2 =  s * (r00 * cX + r01 * cY + r02 * cZ) + tcx;
            float y2 = -(s * (r10 * cX + r11 * cY + r12 * cZ) + tcy);

            // edge 1: v0->v1, edge 2: v1->v2, edge 3: v2->v0
            float e1x = x1 - x0, e1y = y1 - y0;
            float e2x = x2 - x1, e2y = y2 - y1;
            float e3x = x0 - x2, e3y = y0 - y2;
            float il1 = rsqrtf(e1x * e1x + e1y * e1y + 1e-12f);
            float il2 = rsqrtf(e2x * e2x + e2y * e2y + 1e-12f);
            float il3 = rsqrtf(e3x * e3x + e3y * e3y + 1e-12f);
            float ex1 = e1x * il1, ey1 = e1y * il1;
            float ex2 = e2x * il2, ey2 = e2y * il2;
            float ex3 = e3x * il3, ey3 = e3y * il3;

            float A1 = -ey1, t1 = fmaf(ex1, py, ey1 * x0 - ex1 * y0);
            float A2 = -ey2, t2 = fmaf(ex2, py, ey2 * x1 - ex2 * y1);
            float A3 = -ey3, t3 = fmaf(ex3, py, ey3 * x2 - ex3 * y2);

            float area2 = e1x * (y2 - y0) - e1y * (x2 - x0);
            float o = (area2 > 0.f) ? 1.f : ((area2 < 0.f) ? -1.f : 0.f);

            sw[w][lane][0] = make_float4(A1, A2, A3, t1);
            sw[w][lane][1] = make_float4(t2, t3, o, 0.f);
        }
        __syncwarp();

        // ---- pixel loop over this round's 32 faces; vote every 8
        #pragma unroll 1
        for (int g = 0; g < 32 && !done; g += 8) {
            #pragma unroll
            for (int f = g; f < g + 8; ++f) {
                float4 c0 = sw[w][f][0];
                float4 c1 = sw[w][f][1];
                float d1 = fmaf(c0.x, px, c0.w);
                float d2 = fmaf(c0.y, px, c1.x);
                float d3 = fmaf(c0.z, px, c1.y);
                acc = fmaxf(acc, c1.z * fminf(fminf(d1, d2), d3));
            }
            done = (__all_sync(0xffffffffu, acc >= TAU) != 0);
        }
        __syncwarp();   // protect sw[w] reuse next round
    }

    // sigmoid via fast division: exact 1.0 when saturated (exp -> 0)
    float ex = __expf(-SHARP * acc);
    out[(size_t)b * IMG * IMG + (size_t)row * IMG + x] = __fdividef(1.0f, 1.0f + ex);
}

extern "C" void kernel_launch(void* const* d_in, const int* in_sizes, int n_in,
                              void* d_out, int out_size) {
    const float* verts = (const float*)d_in[0];  // [2, 642, 3] f32
    const int*   faces = (const int*)d_in[1];    // [2, 1280, 3] i32
    const float* cams  = (const float*)d_in[2];  // [2, 7] f32
    float* out = (float*)d_out;                  // [2, 256, 256] f32

    // Block covers 1024 px -> grid.x = IMG*IMG/1024 = 64; 128 CTAs total.
    fused_kernel<<<dim3(IMG * IMG / 1024, NBATCH), 1024>>>(verts, faces, cams, out);
}

// round 13
// speedup vs baseline: 1.3264x; 1.3264x over previous
#include <cuda_runtime.h>
#include <math.h>

#define IMG 256
#define NVERT 642
#define NFACE 1280
#define NBATCH 2
#define SHARP (2.0f * (float)IMG)
#define TAU 0.04f    // sigmoid(SHARP*TAU) >= 1 - 1.3e-9: later faces can't change output

// Per-warp autonomous renderer, one CTA per SM (R10 config = best measured).
// Block 512 = 16 warps; block covers 4 rows x 256 px = 1024 px.
// Grid (IMG*IMG/1024, NBATCH) = (64, 2) = 128 CTAs (<=148 SMs -> single wave).
// Warp covers 64 px of row tile*4 + (w>>2), 2 px/lane.
// Each round: 32 lanes compute coefficients for 32 faces (one each, py folded),
// __syncwarp, pixel loop with a saturation vote every 8 faces. No block barriers.
__global__ __launch_bounds__(512) void fused_kernel(const float* __restrict__ verts,
                                                    const int* __restrict__ faces,
                                                    const float* __restrict__ cams,
                                                    float* __restrict__ out) {
    const int b    = blockIdx.y;
    const int tile = blockIdx.x;
    const int t    = threadIdx.x;
    const int w    = t >> 5;          // warp id in block (0..15)
    const int lane = t & 31;

    // Per-warp coefficient slab: [warp][face][2] float4 = (A1,A2,A3,t1),(t2,t3,o,pad)
    __shared__ __align__(16) float4 sw[16][32][2];

    const float* vbase = verts + (size_t)b * NVERT * 3;
    const int*   fbase = faces + (size_t)b * NFACE * 3;

    // ---- start the dependent load chain for round 0 IMMEDIATELY
    const int* fi0 = fbase + (size_t)lane * 3;
    int pi0 = fi0[0];
    int pi1 = fi0[1];
    int pi2 = fi0[2];

    // ---- camera constants (independent broadcast loads; overlap with above)
    const float* cam = cams + b * 7;
    float s   = cam[0];
    float tcx = cam[1];
    float tcy = cam[2];
    float qw = cam[3], qx = cam[4], qy = cam[5], qz = cam[6];
    float qn = rsqrtf(qw * qw + qx * qx + qy * qy + qz * qz);
    qw *= qn; qx *= qn; qy *= qn; qz *= qn;
    const float r00 = 1.f - 2.f * (qy * qy + qz * qz);
    const float r01 = 2.f * (qx * qy - qw * qz);
    const float r02 = 2.f * (qx * qz + qw * qy);
    const float r10 = 2.f * (qx * qy + qw * qz);
    const float r11 = 1.f - 2.f * (qx * qx + qz * qz);
    const float r12 = 2.f * (qy * qz - qw * qx);

    // ---- pixel mapping: 4 rows per tile; warp covers 64 px of one row
    const int row = tile * 4 + (w >> 2);
    const int xs  = ((w & 3) * 32 + lane) * 2;
    const float inv = 2.0f / (float)IMG;
    const float py  = ((float)row + 0.5f) * inv - 1.0f;    // warp-uniform
    const float px0 = ((float)(xs)     + 0.5f) * inv - 1.0f;
    const float px1 = ((float)(xs + 1) + 0.5f) * inv - 1.0f;
    float acc0 = -3.402823466e+38f;
    float acc1 = -3.402823466e+38f;

    bool done = false;
    for (int c = 0; c < NFACE && !done; c += 32) {
        // ---- this lane computes full coefficients for face (c + lane)
        {
            int i0, i1, i2;
            if (c == 0) {           // round 0: indices already in flight
                i0 = pi0; i1 = pi1; i2 = pi2;
            } else {
                const int* fi = fbase + (size_t)(c + lane) * 3;
                i0 = fi[0]; i1 = fi[1]; i2 = fi[2];
            }

            const float* v0 = vbase + (size_t)i0 * 3;
            const float* v1 = vbase + (size_t)i1 * 3;
            const float* v2 = vbase + (size_t)i2 * 3;
            float aX = v0[0], aY = v0[1], aZ = v0[2];
            float bX = v1[0], bY = v1[1], bZ = v1[2];
            float cX = v2[0], cY = v2[1], cZ = v2[2];

            float x0 =  s * (r00 * aX + r01 * aY + r02 * aZ) + tcx;
            float y0 = -(s * (r10 * aX + r11 * aY + r12 * aZ) + tcy);
            float x1 =  s * (r00 * bX + r01 * bY + r02 * bZ) + tcx;
            float y1 = -(s * (r10 * bX + r11 * bY + r12 * bZ) + tcy);
            float x2 =  s * (r00 * cX + r01 * cY + r02 * cZ) + tcx;
            float y2 = -(s * (r10 * cX + r11 * cY + r12 * cZ) + tcy);

            // edge 1: v0->v1, edge 2: v1->v2, edge 3: v2->v0
            float e1x = x1 - x0, e1y = y1 - y0;
            float e2x = x2 - x1, e2y = y2 - y1;
            float e3x = x0 - x2, e3y = y0 - y2;
            float il1 = rsqrtf(e1x * e1x + e1y * e1y + 1e-12f);
            float il2 = rsqrtf(e2x * e2x + e2y * e2y + 1e-12f);
            float il3 = rsqrtf(e3x * e3x + e3y * e3y + 1e-12f);
            float ex1 = e1x * il1, ey1 = e1y * il1;
            float ex2 = e2x * il2, ey2 = e2y * il2;
            float ex3 = e3x * il3, ey3 = e3y * il3;

            float A1 = -ey1, t1 = fmaf(ex1, py, ey1 * x0 - ex1 * y0);
            float A2 = -ey2, t2 = fmaf(ex2, py, ey2 * x1 - ex2 * y1);
            float A3 = -ey3, t3 = fmaf(ex3, py, ey3 * x2 - ex3 * y2);

            float area2 = e1x * (y2 - y0) - e1y * (x2 - x0);
            float o = (area2 > 0.f) ? 1.f : ((area2 < 0.f) ? -1.f : 0.f);

            sw[w][lane][0] = make_float4(A1, A2, A3, t1);
            sw[w][lane][1] = make_float4(t2, t3, o, 0.f);
        }
        __syncwarp();

        // ---- pixel loop over this round's 32 faces; vote every 8
        #pragma unroll 1
        for (int g = 0; g < 32 && !done; g += 8) {
            #pragma unroll
            for (int f = g; f < g + 8; ++f) {
                float4 c0 = sw[w][f][0];
                float4 c1 = sw[w][f][1];
                float o = c1.z;

                float d1 = fmaf(c0.x, px0, c0.w);
                float d2 = fmaf(c0.y, px0, c1.x);
                float d3 = fmaf(c0.z, px0, c1.y);
                acc0 = fmaxf(acc0, o * fminf(fminf(d1, d2), d3));

                d1 = fmaf(c0.x, px1, c0.w);
                d2 = fmaf(c0.y, px1, c1.x);
                d3 = fmaf(c0.z, px1, c1.y);
                acc1 = fmaxf(acc1, o * fminf(fminf(d1, d2), d3));
            }
            float m = fminf(acc0, acc1);
            done = (__all_sync(0xffffffffu, m >= TAU) != 0);
        }
        __syncwarp();   // protect sw[w] reuse next round
    }

    // sigmoid via fast exp/div: exact 1.0 when saturated (exp -> 0)
    float2 res;
    res.x = __fdividef(1.0f, 1.0f + __expf(-SHARP * acc0));
    res.y = __fdividef(1.0f, 1.0f + __expf(-SHARP * acc1));
    float2* op = (float2*)(out + (size_t)b * IMG * IMG + (size_t)row * IMG + xs);
    *op = res;
}

extern "C" void kernel_launch(void* const* d_in, const int* in_sizes, int n_in,
                              void* d_out, int out_size) {
    const float* verts = (const float*)d_in[0];  // [2, 642, 3] f32
    const int*   faces = (const int*)d_in[1];    // [2, 1280, 3] i32
    const float* cams  = (const float*)d_in[2];  // [2, 7] f32
    float* out = (float*)d_out;                  // [2, 256, 256] f32

    // Block covers 1024 px -> grid.x = IMG*IMG/1024 = 64; 128 CTAs total.
    fused_kernel<<<dim3(IMG * IMG / 1024, NBATCH), 512>>>(verts, faces, cams, out);
}